// round 1
// baseline (speedup 1.0000x reference)
#include <cuda_runtime.h>
#include <cuda_bf16.h>

#define NS 128

__global__ __launch_bounds__(256, 8)
void volrend_kernel(const float4* __restrict__ sig4,
                    const float4* __restrict__ rad4,
                    float* __restrict__ out,
                    int nrays)
{
    const int warp_global = (blockIdx.x * blockDim.x + threadIdx.x) >> 5;
    const int lane = threadIdx.x & 31;
    if (warp_global >= nrays) return;

    const float NEARF = 2.0f, FARF = 6.0f;
    const float D = (FARF - NEARF) / (float)(NS - 1);   // 4/127

    // ---- loads (fully coalesced) ----
    // sigma: ray has 128 contiguous floats = 32 float4; lane l takes the l-th.
    const float4 s = sig4[(size_t)warp_global * 32 + lane];
    // radiance: ray has 384 contiguous floats = 96 float4; lane l takes [3l, 3l+3).
    const size_t rbase = (size_t)warp_global * 96 + (size_t)lane * 3;
    const float4 r0 = rad4[rbase + 0];
    const float4 r1 = rad4[rbase + 1];
    const float4 r2 = rad4[rbase + 2];

    const float sv[4]  = { s.x, s.y, s.z, s.w };
    const float rad[4][3] = {
        { r0.x, r0.y, r0.z },
        { r0.w, r1.x, r1.y },
        { r1.z, r1.w, r2.x },
        { r2.y, r2.z, r2.w }
    };

    const int i0 = lane * 4;     // first sample index owned by this lane

    // alpha_i = 1 - exp(-sigma_i * dist_i); t_i = (1 - alpha_i) + 1e-10
    float a[4], t[4];
#pragma unroll
    for (int j = 0; j < 4; ++j) {
        const float dist = (i0 + j == NS - 1) ? 1e10f : D;
        const float e = __expf(-sv[j] * dist);
        a[j] = 1.0f - e;
        t[j] = e + 1e-10f;
    }

    // exclusive warp prefix-product of the per-lane local products
    float scan = t[0] * t[1] * t[2] * t[3];
#pragma unroll
    for (int off = 1; off < 32; off <<= 1) {
        const float v = __shfl_up_sync(0xffffffffu, scan, off);
        if (lane >= off) scan *= v;
    }
    float T = __shfl_up_sync(0xffffffffu, scan, 1);
    if (lane == 0) T = 1.0f;

    // weights + accumulation (inclusive cumprod: multiply t before use)
    float cr = 0.0f, cg = 0.0f, cb = 0.0f, cd = 0.0f;
#pragma unroll
    for (int j = 0; j < 4; ++j) {
        T *= t[j];
        const float w = a[j] * T;
        cr = fmaf(w, rad[j][0], cr);
        cg = fmaf(w, rad[j][1], cg);
        cb = fmaf(w, rad[j][2], cb);
        cd = fmaf(w, NEARF + (float)(i0 + j) * D, cd);
    }

    // warp reduction
#pragma unroll
    for (int off = 16; off; off >>= 1) {
        cr += __shfl_xor_sync(0xffffffffu, cr, off);
        cg += __shfl_xor_sync(0xffffffffu, cg, off);
        cb += __shfl_xor_sync(0xffffffffu, cb, off);
        cd += __shfl_xor_sync(0xffffffffu, cd, off);
    }

    if (lane == 0) {
        out[(size_t)warp_global * 3 + 0] = cr;
        out[(size_t)warp_global * 3 + 1] = cg;
        out[(size_t)warp_global * 3 + 2] = cb;
        out[(size_t)nrays * 3 + warp_global] = cd;   // depth after rgb block
    }
}

extern "C" void kernel_launch(void* const* d_in, const int* in_sizes, int n_in,
                              void* d_out, int out_size)
{
    const float4* sig4 = (const float4*)d_in[0];   // sigmas [B,R,128,1]
    const float4* rad4 = (const float4*)d_in[1];   // radiances [B,R,128,3]
    float* out = (float*)d_out;

    const int nrays = in_sizes[0] / NS;            // B*R = 262144
    const int warps_per_block = 256 / 32;          // 8 rays per block
    const int blocks = (nrays + warps_per_block - 1) / warps_per_block;

    volrend_kernel<<<blocks, 256>>>(sig4, rad4, out, nrays);
}